// round 4
// baseline (speedup 1.0000x reference)
#include <cuda_runtime.h>
#include <cuda_fp16.h>
#include <cstdint>

// ---------------------------------------------------------------------------
// ChebyKAN: out[n,o] = clip( sum_{i,d=0..4} T_d(tanh(clip(x[n,i]))) * coeffs[o,i,d] )
// N=16384, I=2048, O=2048.  T0==1 folded into bias; GEMM K = I*4 = 8192, fp16.
// ldmatrix + mma.sync.m16n8k16 (compute_103 baseline ISA; tcgen05 unavailable).
// TMA bulk-async 3-stage ring; empty-mbarrier recycling (no per-chunk CTA sync).
// ---------------------------------------------------------------------------

#define N_ROWS 16384
#define I_DIM  2048
#define O_DIM  2048
#define KDIM   8192
#define MT     128
#define NT     128
#define NPAIR  (KDIM / 64)           // 128 k-chunks of KC=64
#define NSTG   3
#define TILE_B 16384                 // 128 rows x 128 B (64 fp16)
#define STG_B  (2 * TILE_B)
#define SMEM_TOTAL (1024 + NSTG * STG_B)   // 99328
#define CLAMP10 10.0f

__device__ __align__(1024) unsigned char g_A[(size_t)N_ROWS * KDIM * 2]; // 256 MB
__device__ __align__(1024) unsigned char g_B[(size_t)O_DIM  * KDIM * 2]; //  32 MB
__device__ float g_bias[O_DIM];

static __device__ __forceinline__ uint32_t swz128(uint32_t off) {
    return off ^ ((off >> 3) & 0x70);
}
static __device__ __forceinline__ float clampf(float v) {
    return fminf(fmaxf(v, -CLAMP10), CLAMP10);
}
static __device__ __forceinline__ uint32_t smem_u32(const void* p) {
    return (uint32_t)__cvta_generic_to_shared(p);
}
static __device__ __forceinline__ void mbar_init(uint32_t a, uint32_t cnt) {
    asm volatile("mbarrier.init.shared.b64 [%0], %1;" :: "r"(a), "r"(cnt) : "memory");
}
static __device__ __forceinline__ void mbar_expect_tx(uint32_t a, uint32_t bytes) {
    asm volatile("mbarrier.arrive.expect_tx.shared.b64 _, [%0], %1;" :: "r"(a), "r"(bytes) : "memory");
}
static __device__ __forceinline__ void mbar_arrive(uint32_t a) {
    asm volatile("mbarrier.arrive.shared.b64 _, [%0];" :: "r"(a) : "memory");
}
static __device__ __forceinline__ void mbar_wait(uint32_t a, uint32_t parity) {
    asm volatile(
        "{\n\t.reg .pred P;\n\t"
        "WL_%=:\n\t"
        "mbarrier.try_wait.parity.acquire.cta.shared::cta.b64 P, [%0], %1, 0x989680;\n\t"
        "@P bra.uni WD_%=;\n\t"
        "bra.uni WL_%=;\n\t"
        "WD_%=:\n\t}"
        :: "r"(a), "r"(parity) : "memory");
}
static __device__ __forceinline__ void bulk_g2s(uint32_t dst, const void* src,
                                                uint32_t bytes, uint32_t mbar) {
    asm volatile(
        "cp.async.bulk.shared::cluster.global.mbarrier::complete_tx::bytes [%0], [%1], %2, [%3];"
        :: "r"(dst), "l"(src), "r"(bytes), "r"(mbar) : "memory");
}
static __device__ __forceinline__ void ldsm_x4(uint32_t& r0, uint32_t& r1,
                                               uint32_t& r2, uint32_t& r3, uint32_t a) {
    asm volatile("ldmatrix.sync.aligned.m8n8.x4.shared.b16 {%0,%1,%2,%3}, [%4];"
                 : "=r"(r0), "=r"(r1), "=r"(r2), "=r"(r3) : "r"(a));
}
static __device__ __forceinline__ void mma16816(float* d, const uint32_t* a,
                                                uint32_t b0, uint32_t b1) {
    asm volatile(
        "mma.sync.aligned.m16n8k16.row.col.f32.f16.f16.f32 "
        "{%0,%1,%2,%3}, {%4,%5,%6,%7}, {%8,%9}, {%0,%1,%2,%3};"
        : "+f"(d[0]), "+f"(d[1]), "+f"(d[2]), "+f"(d[3])
        : "r"(a[0]), "r"(a[1]), "r"(a[2]), "r"(a[3]), "r"(b0), "r"(b1));
}

// ---------------- feature map (4 elems/thread, float4 loads) -----------------
__global__ void feat_kernel(const float* __restrict__ x) {
    int idx4 = blockIdx.x * blockDim.x + threadIdx.x;      // over N*I/4
    if (idx4 >= N_ROWS * I_DIM / 4) return;
    int n = idx4 >> 9;                // 512 float4 per row
    int j = idx4 & 511;               // float4 index within row
    float4 xv = reinterpret_cast<const float4*>(x)[idx4];
    float vv[4] = {xv.x, xv.y, xv.z, xv.w};
#pragma unroll
    for (int q = 0; q < 4; ++q) {
        int i = j * 4 + q;
        float v = clampf(vv[q]);
        float e = expf(2.0f * v);
        float t  = (e - 1.0f) / (e + 1.0f);
        float t2 = 2.0f * t * t  - 1.0f;
        float t3 = 2.0f * t * t2 - t;
        float t4 = 2.0f * t * t3 - t2;
        unsigned short h0 = __half_as_ushort(__float2half_rn(t));
        unsigned short h1 = __half_as_ushort(__float2half_rn(t2));
        unsigned short h2 = __half_as_ushort(__float2half_rn(t3));
        unsigned short h3 = __half_as_ushort(__float2half_rn(t4));
        uint2 u = make_uint2((uint32_t)h0 | ((uint32_t)h1 << 16),
                             (uint32_t)h2 | ((uint32_t)h3 << 16));
        uint32_t off = (uint32_t)(n & 127) * 128u + (uint32_t)(i & 15) * 8u;
        size_t base  = ((size_t)((n >> 7) * NPAIR + (i >> 4))) << 14;
        *reinterpret_cast<uint2*>(g_A + base + swz128(off)) = u;
    }
}

// ---------------- repack B + fused bias (one coeffs pass) --------------------
__global__ void repackB_bias_kernel(const float* __restrict__ coeffs) {
    const int o = blockIdx.x;
    float bsum = 0.0f;
    for (int t = 0; t < I_DIM / 256; ++t) {
        int i = t * 256 + threadIdx.x;
        const float* c5 = coeffs + ((size_t)o * I_DIM + i) * 5;
        float c0 = c5[0];
        unsigned short h0 = __half_as_ushort(__float2half_rn(c5[1]));
        unsigned short h1 = __half_as_ushort(__float2half_rn(c5[2]));
        unsigned short h2 = __half_as_ushort(__float2half_rn(c5[3]));
        unsigned short h3 = __half_as_ushort(__float2half_rn(c5[4]));
        uint2 u = make_uint2((uint32_t)h0 | ((uint32_t)h1 << 16),
                             (uint32_t)h2 | ((uint32_t)h3 << 16));
        uint32_t off = (uint32_t)(o & 127) * 128u + (uint32_t)(i & 15) * 8u;
        size_t base  = ((size_t)((o >> 7) * NPAIR + (i >> 4))) << 14;
        *reinterpret_cast<uint2*>(g_B + base + swz128(off)) = u;
        bsum += c0;
    }
    __shared__ float red[256];
    red[threadIdx.x] = bsum;
    __syncthreads();
    for (int off = 128; off > 0; off >>= 1) {
        if (threadIdx.x < off) red[threadIdx.x] += red[threadIdx.x + off];
        __syncthreads();
    }
    if (threadIdx.x == 0) g_bias[o] = red[0];
}

// ---------------- GEMM: 128x128 CTA, 8 warps (4m x 2n), mma.sync -------------
// SMEM: full[s] at sb+s*8, empty[s] at sb+64+s*8 (count 8), stages at sb+1024.
__global__ void __launch_bounds__(256, 2)
gemm_kernel(float* __restrict__ C) {
    extern __shared__ __align__(1024) unsigned char smem[];
    const uint32_t sb = smem_u32(smem);
    const uint32_t stage0 = sb + 1024;

    const int tid  = threadIdx.x;
    const int wid  = tid >> 5, lane = tid & 31;
    const int wm   = wid & 3;
    const int wn   = wid >> 2;
    const int mtile = blockIdx.y, ntile = blockIdx.x;

    if (tid == 0) {
#pragma unroll
        for (int s = 0; s < NSTG; ++s) {
            mbar_init(sb + s * 8, 1);         // full: tx-based
            mbar_init(sb + 64 + s * 8, 8);    // empty: one arrive per warp
        }
    }
    __syncthreads();

    const unsigned char* aSrc = g_A + ((size_t)mtile * NPAIR << 14);
    const unsigned char* bSrc = g_B + ((size_t)ntile * NPAIR << 14);

    if (tid == 0) {
#pragma unroll
        for (int p = 0; p < NSTG; ++p) {
            uint32_t fb = sb + p * 8;
            uint32_t dst = stage0 + p * STG_B;
            mbar_expect_tx(fb, STG_B);
            bulk_g2s(dst,          aSrc + ((size_t)p << 14), TILE_B, fb);
            bulk_g2s(dst + TILE_B, bSrc + ((size_t)p << 14), TILE_B, fb);
        }
    }

    float acc[2][8][4];
#pragma unroll
    for (int mi = 0; mi < 2; ++mi)
#pragma unroll
        for (int ni = 0; ni < 8; ++ni)
#pragma unroll
            for (int r = 0; r < 4; ++r) acc[mi][ni][r] = 0.0f;

    const int g = lane >> 3, r8 = lane & 7;
    const uint32_t aRow = (uint32_t)(wm * 32 + ((g & 1) << 3) + r8);
    const uint32_t bRow = (uint32_t)(wn * 64 + ((g >> 1) << 3) + r8);
    const uint32_t aKb  = (uint32_t)((g >> 1) << 4);
    const uint32_t bKb  = (uint32_t)((g & 1) << 4);

    for (int k = 0; k < NPAIR; ++k) {
        const int sp = k % NSTG;
        const uint32_t pc = (uint32_t)(k / NSTG);
        const uint32_t fb = sb + sp * 8;
        const uint32_t eb = sb + 64 + sp * 8;
        mbar_wait(fb, pc & 1);

        const uint32_t stA = stage0 + sp * STG_B;
        const uint32_t stB = stA + TILE_B;

#pragma unroll
        for (int ks = 0; ks < 4; ++ks) {
            uint32_t a[2][4];
#pragma unroll
            for (int mi = 0; mi < 2; ++mi) {
                uint32_t off = (aRow + mi * 16) * 128u + (uint32_t)(ks * 32) + aKb;
                ldsm_x4(a[mi][0], a[mi][1], a[mi][2], a[mi][3], stA + swz128(off));
            }
            uint32_t b[4][4];
#pragma unroll
            for (int nj = 0; nj < 4; ++nj) {
                uint32_t off = (bRow + nj * 16) * 128u + (uint32_t)(ks * 32) + bKb;
                ldsm_x4(b[nj][0], b[nj][1], b[nj][2], b[nj][3], stB + swz128(off));
            }
            if (ks == 3 && lane == 0) mbar_arrive(eb);   // this warp done reading sp
#pragma unroll
            for (int mi = 0; mi < 2; ++mi)
#pragma unroll
                for (int ni = 0; ni < 8; ++ni)
                    mma16816(acc[mi][ni], a[mi],
                             b[ni >> 1][(ni & 1) * 2], b[ni >> 1][(ni & 1) * 2 + 1]);
        }

        // rotating producer: warp (k&7) refills stage sp for chunk k+NSTG
        if ((k & 7) == wid && lane == 0 && k + NSTG < NPAIR) {
            mbar_wait(eb, pc & 1);            // all 8 warps done reading stage sp
            const int kn = k + NSTG;
            uint32_t dst = stage0 + sp * STG_B;
            mbar_expect_tx(fb, STG_B);
            bulk_g2s(dst,          aSrc + ((size_t)kn << 14), TILE_B, fb);
            bulk_g2s(dst + TILE_B, bSrc + ((size_t)kn << 14), TILE_B, fb);
        }
    }

    // ---------------- epilogue: bias + clamp, float2 stores ------------------
    const int mBase = mtile * MT + wm * 32 + (lane >> 2);
    const int nBase = ntile * NT + wn * 64 + (lane & 3) * 2;

#pragma unroll
    for (int mi = 0; mi < 2; ++mi) {
#pragma unroll
        for (int ni = 0; ni < 8; ++ni) {
            const int n = nBase + ni * 8;
            const float b0 = g_bias[n], b1 = g_bias[n + 1];
            const int m0 = mBase + mi * 16;
            float2 v0, v1;
            v0.x = clampf(acc[mi][ni][0] + b0);
            v0.y = clampf(acc[mi][ni][1] + b1);
            v1.x = clampf(acc[mi][ni][2] + b0);
            v1.y = clampf(acc[mi][ni][3] + b1);
            *reinterpret_cast<float2*>(C + (size_t)m0 * O_DIM + n)       = v0;
            *reinterpret_cast<float2*>(C + (size_t)(m0 + 8) * O_DIM + n) = v1;
        }
    }
}

// ---------------------------------------------------------------------------
extern "C" void kernel_launch(void* const* d_in, const int* in_sizes, int n_in,
                              void* d_out, int out_size) {
    const float* x      = (const float*)d_in[0];
    const float* coeffs = (const float*)d_in[1];
    float* out          = (float*)d_out;

    cudaFuncSetAttribute(gemm_kernel, cudaFuncAttributeMaxDynamicSharedMemorySize, SMEM_TOTAL);

    feat_kernel        <<<(N_ROWS * I_DIM / 4 + 255) / 256, 256>>>(x);
    repackB_bias_kernel<<<O_DIM, 256>>>(coeffs);
    gemm_kernel        <<<dim3(O_DIM / NT, N_ROWS / MT), 256, SMEM_TOTAL>>>(out);
}

// round 5
// speedup vs baseline: 1.1244x; 1.1244x over previous
#include <cuda_runtime.h>
#include <cuda_fp16.h>
#include <cstdint>

// ---------------------------------------------------------------------------
// ChebyKAN: out[n,o] = clip( sum_{i,d=0..4} T_d(tanh(clip(x[n,i]))) * coeffs[o,i,d] )
// N=16384, I=2048, O=2048.  T0==1 folded into bias; GEMM K = I*4 = 8192, fp16.
// ldmatrix + mma.sync.m16n8k16 (compute_103 baseline ISA; tcgen05 unavailable).
// TMA bulk-async 3-stage ring with per-chunk __syncthreads recycling (R3 scheme).
// feat_kernel uses 16B stores (SW128 swizzle preserves 16B contiguity).
// ---------------------------------------------------------------------------

#define N_ROWS 16384
#define I_DIM  2048
#define O_DIM  2048
#define KDIM   8192
#define MT     128
#define NT     128
#define NPAIR  (KDIM / 64)           // 128 k-chunks of KC=64
#define NSTG   3
#define TILE_B 16384                 // 128 rows x 128 B (64 fp16)
#define STG_B  (2 * TILE_B)
#define SMEM_TOTAL (1024 + NSTG * STG_B)   // 99328
#define CLAMP10 10.0f

__device__ __align__(1024) unsigned char g_A[(size_t)N_ROWS * KDIM * 2]; // 256 MB
__device__ __align__(1024) unsigned char g_B[(size_t)O_DIM  * KDIM * 2]; //  32 MB
__device__ float g_bias[O_DIM];

static __device__ __forceinline__ uint32_t swz128(uint32_t off) {
    return off ^ ((off >> 3) & 0x70);
}
static __device__ __forceinline__ float clampf(float v) {
    return fminf(fmaxf(v, -CLAMP10), CLAMP10);
}
static __device__ __forceinline__ uint32_t smem_u32(const void* p) {
    return (uint32_t)__cvta_generic_to_shared(p);
}
static __device__ __forceinline__ void mbar_init(uint32_t a, uint32_t cnt) {
    asm volatile("mbarrier.init.shared.b64 [%0], %1;" :: "r"(a), "r"(cnt) : "memory");
}
static __device__ __forceinline__ void mbar_expect_tx(uint32_t a, uint32_t bytes) {
    asm volatile("mbarrier.arrive.expect_tx.shared.b64 _, [%0], %1;" :: "r"(a), "r"(bytes) : "memory");
}
static __device__ __forceinline__ void mbar_wait(uint32_t a, uint32_t parity) {
    asm volatile(
        "{\n\t.reg .pred P;\n\t"
        "WL_%=:\n\t"
        "mbarrier.try_wait.parity.acquire.cta.shared::cta.b64 P, [%0], %1, 0x989680;\n\t"
        "@P bra.uni WD_%=;\n\t"
        "bra.uni WL_%=;\n\t"
        "WD_%=:\n\t}"
        :: "r"(a), "r"(parity) : "memory");
}
static __device__ __forceinline__ void bulk_g2s(uint32_t dst, const void* src,
                                                uint32_t bytes, uint32_t mbar) {
    asm volatile(
        "cp.async.bulk.shared::cluster.global.mbarrier::complete_tx::bytes [%0], [%1], %2, [%3];"
        :: "r"(dst), "l"(src), "r"(bytes), "r"(mbar) : "memory");
}
static __device__ __forceinline__ void ldsm_x4(uint32_t& r0, uint32_t& r1,
                                               uint32_t& r2, uint32_t& r3, uint32_t a) {
    asm volatile("ldmatrix.sync.aligned.m8n8.x4.shared.b16 {%0,%1,%2,%3}, [%4];"
                 : "=r"(r0), "=r"(r1), "=r"(r2), "=r"(r3) : "r"(a));
}
static __device__ __forceinline__ void mma16816(float* d, const uint32_t* a,
                                                uint32_t b0, uint32_t b1) {
    asm volatile(
        "mma.sync.aligned.m16n8k16.row.col.f32.f16.f16.f32 "
        "{%0,%1,%2,%3}, {%4,%5,%6,%7}, {%8,%9}, {%0,%1,%2,%3};"
        : "+f"(d[0]), "+f"(d[1]), "+f"(d[2]), "+f"(d[3])
        : "r"(a[0]), "r"(a[1]), "r"(a[2]), "r"(a[3]), "r"(b0), "r"(b1));
}

// ---------------- feature map: 4 elems/thread, 2x 16B swizzled stores --------
__global__ void feat_kernel(const float* __restrict__ x) {
    int idx4 = blockIdx.x * blockDim.x + threadIdx.x;      // over N*I/4
    if (idx4 >= N_ROWS * I_DIM / 4) return;
    const int n = idx4 >> 9;            // 512 float4 per row
    const int j = idx4 & 511;           // float4 index within row
    float4 xv = reinterpret_cast<const float4*>(x)[idx4];
    float vv[4] = {xv.x, xv.y, xv.z, xv.w};
    uint32_t u[8];                      // 4 elems x (2x fp16x2)
#pragma unroll
    for (int q = 0; q < 4; ++q) {
        float v = clampf(vv[q]);
        float e = expf(2.0f * v);
        float t  = (e - 1.0f) / (e + 1.0f);
        float t2 = 2.0f * t * t  - 1.0f;
        float t3 = 2.0f * t * t2 - t;
        float t4 = 2.0f * t * t3 - t2;
        unsigned short h0 = __half_as_ushort(__float2half_rn(t));
        unsigned short h1 = __half_as_ushort(__float2half_rn(t2));
        unsigned short h2 = __half_as_ushort(__float2half_rn(t3));
        unsigned short h3 = __half_as_ushort(__float2half_rn(t4));
        u[q * 2 + 0] = (uint32_t)h0 | ((uint32_t)h1 << 16);
        u[q * 2 + 1] = (uint32_t)h2 | ((uint32_t)h3 << 16);
    }
    // i = j*4 + q; all 4 q share tile (i>>4 == j>>2); cols (i&15) are a
    // 32B-aligned group of 4 -> two 16B pieces, each contiguous post-swizzle.
    const int i0 = j * 4;
    const uint32_t off0 = (uint32_t)(n & 127) * 128u + (uint32_t)(i0 & 15) * 8u;
    const size_t  base  = ((size_t)((n >> 7) * NPAIR + (i0 >> 4))) << 14;
    *reinterpret_cast<uint4*>(g_A + base + swz128(off0)) =
        make_uint4(u[0], u[1], u[2], u[3]);
    *reinterpret_cast<uint4*>(g_A + base + swz128(off0 + 16)) =
        make_uint4(u[4], u[5], u[6], u[7]);
}

// ---------------- repack B + fused bias (one coeffs pass) --------------------
__global__ void repackB_bias_kernel(const float* __restrict__ coeffs) {
    const int o = blockIdx.x;
    float bsum = 0.0f;
    for (int t = 0; t < I_DIM / 256; ++t) {
        int i = t * 256 + threadIdx.x;
        const float* c5 = coeffs + ((size_t)o * I_DIM + i) * 5;
        float c0 = c5[0];
        unsigned short h0 = __half_as_ushort(__float2half_rn(c5[1]));
        unsigned short h1 = __half_as_ushort(__float2half_rn(c5[2]));
        unsigned short h2 = __half_as_ushort(__float2half_rn(c5[3]));
        unsigned short h3 = __half_as_ushort(__float2half_rn(c5[4]));
        uint2 u = make_uint2((uint32_t)h0 | ((uint32_t)h1 << 16),
                             (uint32_t)h2 | ((uint32_t)h3 << 16));
        uint32_t off = (uint32_t)(o & 127) * 128u + (uint32_t)(i & 15) * 8u;
        size_t base  = ((size_t)((o >> 7) * NPAIR + (i >> 4))) << 14;
        *reinterpret_cast<uint2*>(g_B + base + swz128(off)) = u;
        bsum += c0;
    }
    __shared__ float red[256];
    red[threadIdx.x] = bsum;
    __syncthreads();
    for (int off = 128; off > 0; off >>= 1) {
        if (threadIdx.x < off) red[threadIdx.x] += red[threadIdx.x + off];
        __syncthreads();
    }
    if (threadIdx.x == 0) g_bias[o] = red[0];
}

// ---------------- GEMM: 128x128 CTA tile, 8 warps (4m x 2n), mma.sync -------
__global__ void __launch_bounds__(256, 2)
gemm_kernel(float* __restrict__ C) {
    extern __shared__ __align__(1024) unsigned char smem[];
    const uint32_t sb = smem_u32(smem);
    const uint32_t stage0 = sb + 1024;

    const int tid  = threadIdx.x;
    const int wid  = tid >> 5, lane = tid & 31;
    const int wm   = wid & 3;          // 0..3 -> 32-row slice of M tile
    const int wn   = wid >> 2;         // 0..1 -> 64-col slice of N tile
    const int mtile = blockIdx.y, ntile = blockIdx.x;

    if (tid == 0) {
#pragma unroll
        for (int s = 0; s < NSTG; ++s) mbar_init(sb + s * 8, 1);
    }
    __syncthreads();

    const unsigned char* aSrc = g_A + ((size_t)mtile * NPAIR << 14);
    const unsigned char* bSrc = g_B + ((size_t)ntile * NPAIR << 14);

    if (tid == 0) {
#pragma unroll
        for (int p = 0; p < NSTG; ++p) {
            uint32_t fb = sb + p * 8;
            uint32_t dst = stage0 + p * STG_B;
            mbar_expect_tx(fb, STG_B);
            bulk_g2s(dst,          aSrc + ((size_t)p << 14), TILE_B, fb);
            bulk_g2s(dst + TILE_B, bSrc + ((size_t)p << 14), TILE_B, fb);
        }
    }

    float acc[2][8][4];
#pragma unroll
    for (int mi = 0; mi < 2; ++mi)
#pragma unroll
        for (int ni = 0; ni < 8; ++ni)
#pragma unroll
            for (int r = 0; r < 4; ++r) acc[mi][ni][r] = 0.0f;

    const int g = lane >> 3, r8 = lane & 7;
    const uint32_t aRow = (uint32_t)(wm * 32 + ((g & 1) << 3) + r8);
    const uint32_t bRow = (uint32_t)(wn * 64 + ((g >> 1) << 3) + r8);
    const uint32_t aKb  = (uint32_t)((g >> 1) << 4);
    const uint32_t bKb  = (uint32_t)((g & 1) << 4);

    for (int k = 0; k < NPAIR; ++k) {
        const int sp = k % NSTG;
        const uint32_t fb = sb + sp * 8;
        mbar_wait(fb, (uint32_t)((k / NSTG) & 1));

        const uint32_t stA = stage0 + sp * STG_B;
        const uint32_t stB = stA + TILE_B;

#pragma unroll
        for (int ks = 0; ks < 4; ++ks) {
            uint32_t a[2][4];
#pragma unroll
            for (int mi = 0; mi < 2; ++mi) {
                uint32_t off = (aRow + mi * 16) * 128u + (uint32_t)(ks * 32) + aKb;
                ldsm_x4(a[mi][0], a[mi][1], a[mi][2], a[mi][3], stA + swz128(off));
            }
            uint32_t b[4][4];
#pragma unroll
            for (int nj = 0; nj < 4; ++nj) {
                uint32_t off = (bRow + nj * 16) * 128u + (uint32_t)(ks * 32) + bKb;
                ldsm_x4(b[nj][0], b[nj][1], b[nj][2], b[nj][3], stB + swz128(off));
            }
#pragma unroll
            for (int mi = 0; mi < 2; ++mi)
#pragma unroll
                for (int ni = 0; ni < 8; ++ni)
                    mma16816(acc[mi][ni], a[mi],
                             b[ni >> 1][(ni & 1) * 2], b[ni >> 1][(ni & 1) * 2 + 1]);
        }

        __syncthreads();   // all warps done reading stage sp
        if (tid == 0 && k + NSTG < NPAIR) {
            const int kn = k + NSTG;
            uint32_t dst = stage0 + sp * STG_B;
            mbar_expect_tx(fb, STG_B);
            bulk_g2s(dst,          aSrc + ((size_t)kn << 14), TILE_B, fb);
            bulk_g2s(dst + TILE_B, bSrc + ((size_t)kn << 14), TILE_B, fb);
        }
    }

    // ---------------- epilogue: bias + clamp, float2 stores ------------------
    const int mBase = mtile * MT + wm * 32 + (lane >> 2);
    const int nBase = ntile * NT + wn * 64 + (lane & 3) * 2;

#pragma unroll
    for (int mi = 0; mi < 2; ++mi) {
#pragma unroll
        for (int ni = 0; ni < 8; ++ni) {
            const int n = nBase + ni * 8;
            const float b0 = g_bias[n], b1 = g_bias[n + 1];
            const int m0 = mBase + mi * 16;
            float2 v0, v1;
            v0.x = clampf(acc[mi][ni][0] + b0);
            v0.y = clampf(acc[mi][ni][1] + b1);
            v1.x = clampf(acc[mi][ni][2] + b0);
            v1.y = clampf(acc[mi][ni][3] + b1);
            *reinterpret_cast<float2*>(C + (size_t)m0 * O_DIM + n)       = v0;
            *reinterpret_cast<float2*>(C + (size_t)(m0 + 8) * O_DIM + n) = v1;
        }
    }
}

// ---------------------------------------------------------------------------
extern "C" void kernel_launch(void* const* d_in, const int* in_sizes, int n_in,
                              void* d_out, int out_size) {
    const float* x      = (const float*)d_in[0];
    const float* coeffs = (const float*)d_in[1];
    float* out          = (float*)d_out;

    cudaFuncSetAttribute(gemm_kernel, cudaFuncAttributeMaxDynamicSharedMemorySize, SMEM_TOTAL);

    feat_kernel        <<<(N_ROWS * I_DIM / 4 + 255) / 256, 256>>>(x);
    repackB_bias_kernel<<<O_DIM, 256>>>(coeffs);
    gemm_kernel        <<<dim3(O_DIM / NT, N_ROWS / MT), 256, SMEM_TOTAL>>>(out);
}